// round 14
// baseline (speedup 1.0000x reference)
#include <cuda_runtime.h>
#include <cstdint>

#define TT 512      // time steps
#define NB 512      // batch
#define CC 80       // classes
#define SS 128      // max target len
#define WPB 2       // warps per block
#define NSPW 2      // batch elems (streams) per warp
#define NBC (NB*CC) // row stride in floats
#define EMROW 336   // bytes per em slot (84 floats)

static __device__ __forceinline__ unsigned smem_u32(const void* p) {
    return (unsigned)__cvta_generic_to_shared(p);
}
template <int IMM>
static __device__ __forceinline__ float lds_imm(unsigned addr) {
    float v;
    asm volatile("ld.shared.f32 %0, [%1+%2];" : "=f"(v) : "r"(addr), "n"(IMM));
    return v;
}
static __device__ __forceinline__ float lds_reg(unsigned addr) {
    float v;
    asm volatile("ld.shared.f32 %0, [%1];" : "=f"(v) : "r"(addr));
    return v;
}
static __device__ __forceinline__ float exp2c(int e) {
    e = max(-126, min(127, e));
    return __int_as_float((e + 127) << 23);
}
static __device__ __forceinline__ float4 exp4(float4 r) {
    float4 p;
    p.x = __expf(r.x); p.y = __expf(r.y); p.z = __expf(r.z); p.w = __expf(r.w);
    return p;
}

struct WState {
    float a[9];      // cells s = 8*lane + j; a[8] = cell 256 (lane 31 only)
    float sk[4];     // skip multiplier for label cells j=1,3,5,7
    unsigned coL[4]; // smem addr (slot 0) of label emission for j=1,3,5,7
    unsigned emu;    // smem addr (slot 0) of blank emission
    float m31;       // 1.0 on lane 31 else 0
    float pAr;       // boundary alpha a[7] from lane-1 (pre-rescale snapshot)
    int elane;       // per-lane exponent: true alpha = a * 2^elane
    int eprev;       // lane-1's elane at snapshot time
    bool empty;      // lane has no probability mass yet
};

template <bool RESC, bool FREEZE>
static __device__ __forceinline__ void ctc_core(
    WState& S, int lane, float gb, float g0, float g1, float g2, float g3, bool act)
{
    // exponent alignment with left neighbor (branch-free; empty lanes adopt)
    int de = S.eprev - S.elane;
    S.elane = S.empty ? S.eprev : S.elane;
    de      = S.empty ? 0 : de;
    float f  = exp2c(de);
    float pA = S.pAr * f;

    // new cell values (all read old state)
    float n8 = fmaf(S.m31, S.a[7], S.a[8]) * gb;
    float n7; { float tv = S.a[7] + S.a[6]; tv = fmaf(S.a[5], S.sk[3], tv); n7 = tv * g3; }
    float n6 = (S.a[6] + S.a[5]) * gb;
    float n5; { float tv = S.a[5] + S.a[4]; tv = fmaf(S.a[3], S.sk[2], tv); n5 = tv * g2; }
    float n4 = (S.a[4] + S.a[3]) * gb;
    float n3; { float tv = S.a[3] + S.a[2]; tv = fmaf(S.a[1], S.sk[1], tv); n3 = tv * g1; }
    float n2 = (S.a[2] + S.a[1]) * gb;
    float n1; { float tv = S.a[1] + S.a[0]; tv = fmaf(pA,     S.sk[0], tv); n1 = tv * g0; }
    float n0 = (S.a[0] + pA) * gb;

    if (FREEZE) {
        S.a[0] = act ? n0 : S.a[0]; S.a[1] = act ? n1 : S.a[1];
        S.a[2] = act ? n2 : S.a[2]; S.a[3] = act ? n3 : S.a[3];
        S.a[4] = act ? n4 : S.a[4]; S.a[5] = act ? n5 : S.a[5];
        S.a[6] = act ? n6 : S.a[6]; S.a[7] = act ? n7 : S.a[7];
        S.a[8] = act ? n8 : S.a[8];
    } else {
        S.a[0] = n0; S.a[1] = n1; S.a[2] = n2; S.a[3] = n3; S.a[4] = n4;
        S.a[5] = n5; S.a[6] = n6; S.a[7] = n7; S.a[8] = n8;
    }

    if (pA > 0.f) S.empty = false;   // only entry point for new mass

    // boundary snapshot for NEXT step (pre-rescale value + current exponent)
    S.pAr   = __shfl_up_sync(0xffffffffu, S.a[7], 1);
    S.eprev = __shfl_up_sync(0xffffffffu, S.elane, 1);
    if (lane == 0) { S.pAr = 0.f; S.eprev = S.elane; }

    if (RESC) {   // branch-free per-lane power-of-2 renormalization (repr-only)
        float m = fmaxf(fmaxf(fmaxf(S.a[0], S.a[1]), fmaxf(S.a[2], S.a[3])),
                        fmaxf(fmaxf(S.a[4], S.a[5]),
                              fmaxf(fmaxf(S.a[6], S.a[7]), S.a[8])));
        bool nz = m > 0.f;
        int e = nz ? (((__float_as_int(m) >> 23) & 255) - 127) : 0;
        float sc = exp2c(-e);
#pragma unroll
        for (int j = 0; j < 9; j++) S.a[j] *= sc;
        S.elane += e;
        S.empty = !nz;
    }
}

template <int SLOT, bool RESC, bool FREEZE>
static __device__ __forceinline__ void ctc_step(WState& S, int lane, bool act)
{
    float gb = lds_imm<SLOT * EMROW>(S.emu);
    float g0 = lds_imm<SLOT * EMROW>(S.coL[0]);
    float g1 = lds_imm<SLOT * EMROW>(S.coL[1]);
    float g2 = lds_imm<SLOT * EMROW>(S.coL[2]);
    float g3 = lds_imm<SLOT * EMROW>(S.coL[3]);
    ctc_core<RESC, FREEZE>(S, lane, gb, g0, g1, g2, g3, act);
}
static __device__ __forceinline__ void ctc_step_rt(WState& S, int lane, unsigned off, bool act)
{
    float gb = lds_reg(S.emu + off);
    float g0 = lds_reg(S.coL[0] + off);
    float g1 = lds_reg(S.coL[1] + off);
    float g2 = lds_reg(S.coL[2] + off);
    float g3 = lds_reg(S.coL[3] + off);
    ctc_core<true, true>(S, lane, gb, g0, g1, g2, g3, act);
}

// 4-step block for both streams: steps tb..tb+3 (slots 1,2,3,0),
// convert Q (rows tb+4..tb+7), refill Q with rows tb+8..tb+11.
template <bool FREEZE>
static __device__ __forceinline__ void block4(
    WState& S0, WState& S1, int lane, char* e0, char* e1,
    float4 (&Q0)[4], float4 (&Q1)[4],
    const float* gQ0, const float* gQ1, int tb, int Tn0, int Tn1)
{
    const bool ld = lane < 20;
    ctc_step<1, false, FREEZE>(S0, lane, tb + 0 < Tn0);
    ctc_step<1, false, FREEZE>(S1, lane, tb + 0 < Tn1);
    if (ld) { *(float4*)(e0 + 1 * EMROW) = exp4(Q0[0]);
              *(float4*)(e1 + 1 * EMROW) = exp4(Q1[0]); }
    ctc_step<2, true, FREEZE>(S0, lane, tb + 1 < Tn0);
    ctc_step<2, true, FREEZE>(S1, lane, tb + 1 < Tn1);
    if (ld) { *(float4*)(e0 + 2 * EMROW) = exp4(Q0[1]);
              *(float4*)(e1 + 2 * EMROW) = exp4(Q1[1]); }
    ctc_step<3, false, FREEZE>(S0, lane, tb + 2 < Tn0);
    ctc_step<3, false, FREEZE>(S1, lane, tb + 2 < Tn1);
    if (ld) { *(float4*)(e0 + 3 * EMROW) = exp4(Q0[2]);
              *(float4*)(e1 + 3 * EMROW) = exp4(Q1[2]); }
    ctc_step<0, true, FREEZE>(S0, lane, tb + 3 < Tn0);
    ctc_step<0, true, FREEZE>(S1, lane, tb + 3 < Tn1);
    if (ld) {
        *(float4*)(e0 + 0 * EMROW) = exp4(Q0[3]);
        *(float4*)(e1 + 0 * EMROW) = exp4(Q1[3]);
#pragma unroll
        for (int k = 0; k < 4; k++) {
            if (tb + 8 + k < TT) {
                Q0[k] = *(const float4*)(gQ0 + (size_t)k * NBC);
                Q1[k] = *(const float4*)(gQ1 + (size_t)k * NBC);
            }
        }
    }
    __syncwarp();
}

static __device__ __forceinline__ void init_state(
    WState& S, const int* trow, unsigned emu, int lane)
{
    S.emu = emu;
    S.m31 = (lane == 31) ? 1.f : 0.f;
#pragma unroll
    for (int j = 0; j < 9; j++) S.a[j] = 0.f;
#pragma unroll
    for (int jj = 0; jj < 4; jj++) {     // label cells j = 2*jj+1
        int k = 4 * lane + jj;           // label index < 128
        int c = trow[k];
        S.coL[jj] = emu + (unsigned)c * 4;
        S.sk[jj]  = (k >= 1 && trow[k - 1] != c) ? 1.f : 0.f;
    }
    S.elane = 0;
    S.empty = (lane != 0);
    S.pAr = 0.f;
    S.eprev = 0;
}

__global__ __launch_bounds__(WPB * 32)
void ctc_kernel(const float* __restrict__ lp,   // (T, N, C)
                const int*   __restrict__ tgt,  // (N, S)
                const int*   __restrict__ ilen, // (N,)
                const int*   __restrict__ tlen, // (N,)
                float*       __restrict__ out,  // (N,)
                int nb)
{
    __shared__ __align__(16) float em[WPB * NSPW][4][84]; // em rings (slot = row & 3)
    __shared__ float dmp[WPB * NSPW][264];                // finalize dumps
    __shared__ int ed[WPB * NSPW][32];                    // per-lane exponents

    const int lane = threadIdx.x & 31;
    const int w    = threadIdx.x >> 5;
    const int n0   = (blockIdx.x * WPB + w) * NSPW;
    if (n0 >= nb) return;

    const int si0 = w * NSPW, si1 = si0 + 1;
    char* emb0 = (char*)&em[si0][0][0] + lane * 16;
    char* emb1 = (char*)&em[si1][0][0] + lane * 16;
    const unsigned emu0 = smem_u32(&em[si0][0][0]);
    const unsigned emu1 = smem_u32(&em[si1][0][0]);

    const int Tn0 = ilen[n0], Tn1 = ilen[n0 + 1];
    const int tl0 = tlen[n0], tl1 = tlen[n0 + 1];
    const int Tmin = min(Tn0, Tn1), Tmax = max(Tn0, Tn1);

    WState S0, S1;
    init_state(S0, tgt + (size_t)n0 * SS,       emu0, lane);
    init_state(S1, tgt + (size_t)(n0 + 1) * SS, emu1, lane);

    const float* gl0 = lp + (size_t)n0 * CC + lane * 4;
    const float* gl1 = lp + (size_t)(n0 + 1) * CC + lane * 4;

    // ---- prologue: LDG rows 0..4, convert rows 0..4, refill rows 5..8 ----
    const bool ld = lane < 20;
    float4 z = make_float4(0.f, 0.f, 0.f, 0.f);
    float4 Q0[4] = {z, z, z, z}, Q1[4] = {z, z, z, z};
    float4 r00 = z, r01 = z;
    if (ld) {
        r00 = *(const float4*)gl0;
        r01 = *(const float4*)gl1;
#pragma unroll
        for (int k = 0; k < 4; k++) {
            Q0[k] = *(const float4*)(gl0 + (size_t)(1 + k) * NBC);
            Q1[k] = *(const float4*)(gl1 + (size_t)(1 + k) * NBC);
        }
    }
    if (ld) {
        *(float4*)(emb0 + 0 * EMROW) = exp4(r00);   // row 0 -> slot 0
        *(float4*)(emb1 + 0 * EMROW) = exp4(r01);
    }
    __syncwarp();
    if (lane == 0) {   // alpha at t=0: lattice positions 0 and 1
        S0.a[0] = lds_reg(S0.emu); S0.a[1] = lds_reg(S0.coL[0]);
        S1.a[0] = lds_reg(S1.emu); S1.a[1] = lds_reg(S1.coL[0]);
    }
    if (ld) {   // rows 1..3 -> slots 1..3
#pragma unroll
        for (int r = 0; r < 3; r++) {
            *(float4*)(emb0 + (r + 1) * EMROW) = exp4(Q0[r]);
            *(float4*)(emb1 + (r + 1) * EMROW) = exp4(Q1[r]);
        }
    }
    __syncwarp();   // slot-0 init reads done before row-4 overwrite
    if (ld) {
        *(float4*)(emb0 + 0 * EMROW) = exp4(Q0[3]);  // row 4 -> slot 0
        *(float4*)(emb1 + 0 * EMROW) = exp4(Q1[3]);
#pragma unroll
        for (int k = 0; k < 4; k++) {                // refill rows 5..8
            Q0[k] = *(const float4*)(gl0 + (size_t)(5 + k) * NBC);
            Q1[k] = *(const float4*)(gl1 + (size_t)(5 + k) * NBC);
        }
    }
    // initial boundary snapshots
    S0.pAr   = __shfl_up_sync(0xffffffffu, S0.a[7], 1);
    S0.eprev = __shfl_up_sync(0xffffffffu, S0.elane, 1);
    S1.pAr   = __shfl_up_sync(0xffffffffu, S1.a[7], 1);
    S1.eprev = __shfl_up_sync(0xffffffffu, S1.elane, 1);
    if (lane == 0) {
        S0.pAr = 0.f; S0.eprev = S0.elane;
        S1.pAr = 0.f; S1.eprev = S1.elane;
    }
    __syncwarp();

    // ---- main loops ----
    int t = 1;
    for (; t + 3 < Tmin; t += 4)     // both streams active: no freeze selects
        block4<false>(S0, S1, lane, emb0, emb1, Q0, Q1,
                      gl0 + (size_t)(t + 8) * NBC, gl1 + (size_t)(t + 8) * NBC,
                      t, Tn0, Tn1);
    for (; t + 3 < Tmax; t += 4)     // shorter stream frozen via selects
        block4<true>(S0, S1, lane, emb0, emb1, Q0, Q1,
                     gl0 + (size_t)(t + 8) * NBC, gl1 + (size_t)(t + 8) * NBC,
                     t, Tn0, Tn1);
    for (; t < Tmax; t++) {          // tail: em rows already converted
        unsigned off = (unsigned)((t & 3) * EMROW);
        ctc_step_rt(S0, lane, off, t < Tn0);
        ctc_step_rt(S1, lane, off, t < Tn1);
    }

    // ---- finalize both streams ----
    __syncwarp();
#pragma unroll
    for (int j = 0; j < 8; j++) {
        dmp[si0][8 * lane + j] = S0.a[j];
        dmp[si1][8 * lane + j] = S1.a[j];
    }
    if (lane == 31) { dmp[si0][256] = S0.a[8]; dmp[si1][256] = S1.a[8]; }
    ed[si0][lane] = S0.elane;
    ed[si1][lane] = S1.elane;
    __syncwarp();
    if (lane < 2) {
        int si = si0 + lane;
        int tl = lane ? tl1 : tl0;
        int s1 = 2 * tl, s2 = s1 - 1;
        float va = dmp[si][s1]; int ea = ed[si][min(s1 >> 3, 31)];
        float vb = dmp[si][s2]; int eb = ed[si][s2 >> 3];
        int emax = max(ea, eb);
        float v = va * exp2c(ea - emax) + vb * exp2c(eb - emax);
        float loss = -((__log2f(v) + (float)emax) * 0.69314718055994530942f);
        if (!isfinite(loss) || !(loss < 1e10f)) loss = 0.f;  // zero_infinity
        out[n0 + lane] = loss;
    }
}

extern "C" void kernel_launch(void* const* d_in, const int* in_sizes, int n_in,
                              void* d_out, int out_size) {
    const float* lp   = (const float*)d_in[0];
    const int*   tgt  = (const int*)d_in[1];
    const int*   ilen = (const int*)d_in[2];
    const int*   tlen = (const int*)d_in[3];
    float*       out  = (float*)d_out;
    int nb = out_size;                                   // N
    int blocks = (nb + WPB * NSPW - 1) / (WPB * NSPW);   // 128
    ctc_kernel<<<blocks, WPB * 32>>>(lp, tgt, ilen, tlen, out, nb);
}

// round 15
// speedup vs baseline: 1.3303x; 1.3303x over previous
#include <cuda_runtime.h>
#include <cstdint>

#define TT 512      // time steps
#define NB 512      // batch
#define CC 80       // classes
#define SS 128      // max target len
#define WPB 4       // warps (batch elems) per block
#define NBC (NB*CC) // row stride in floats
#define EMROW 336   // bytes per em slot (84 floats; 80 used)

static __device__ __forceinline__ unsigned smem_u32(const void* p) {
    return (unsigned)__cvta_generic_to_shared(p);
}
template <int IMM>
static __device__ __forceinline__ float lds_imm(unsigned addr) {
    float v;
    asm volatile("ld.shared.f32 %0, [%1+%2];" : "=f"(v) : "r"(addr), "n"(IMM));
    return v;
}
static __device__ __forceinline__ float lds_reg(unsigned addr) {
    float v;
    asm volatile("ld.shared.f32 %0, [%1];" : "=f"(v) : "r"(addr));
    return v;
}
// exact power of two 2^e, exponent clamped to normal range
static __device__ __forceinline__ float exp2c(int e) {
    e = max(-126, min(127, e));
    return __int_as_float((e + 127) << 23);
}
static __device__ __forceinline__ float4 exp4(float4 r) {
    float4 p;
    p.x = __expf(r.x); p.y = __expf(r.y); p.z = __expf(r.z); p.w = __expf(r.w);
    return p;
}

struct WState {
    float a[9];      // cells s = 8*lane + j (j=0..7); a[8] = cell 256, lane 31 only
    float sk[4];     // skip multiplier for label cells j=1,3,5,7
    unsigned coL[4]; // smem addr (slot 0) of label emission for j=1,3,5,7
    unsigned emu;    // smem addr (slot 0) of blank emission (class 0)
    float m31;       // 1.0 on lane 31, else 0 (gates cell 256)
    float pAr;       // boundary alpha a[7] from lane-1 (pre-rescale snapshot)
    int elane;       // per-lane exponent: true alpha = a * 2^elane
    int eprev;       // lane-1's elane at snapshot time
    bool empty;      // lane has no probability mass yet
};

// Core recurrence given gathered emissions g[5] = {blank, label0..3}.
template <bool RESC>
static __device__ __forceinline__ void ctc_core(WState& S, int lane, const float (&g)[5])
{
    // exponent alignment with left neighbor (branch-free; empty lanes adopt)
    int de = S.eprev - S.elane;
    S.elane = S.empty ? S.eprev : S.elane;
    de      = S.empty ? 0 : de;
    float f  = exp2c(de);
    float pA = S.pAr * f;

    // descending update: old values read before overwrite
    S.a[8] = fmaf(S.m31, S.a[7], S.a[8]) * g[0];                              // s=256 (blank, lane31)
    { float tv = S.a[7] + S.a[6]; tv = fmaf(S.a[5], S.sk[3], tv); S.a[7] = tv * g[4]; }
    S.a[6] = (S.a[6] + S.a[5]) * g[0];                                        // blank: no skip
    { float tv = S.a[5] + S.a[4]; tv = fmaf(S.a[3], S.sk[2], tv); S.a[5] = tv * g[3]; }
    S.a[4] = (S.a[4] + S.a[3]) * g[0];
    { float tv = S.a[3] + S.a[2]; tv = fmaf(S.a[1], S.sk[1], tv); S.a[3] = tv * g[2]; }
    S.a[2] = (S.a[2] + S.a[1]) * g[0];
    { float tv = S.a[1] + S.a[0]; tv = fmaf(pA,     S.sk[0], tv); S.a[1] = tv * g[1]; }
    S.a[0] = (S.a[0] + pA) * g[0];

    if (pA > 0.f) S.empty = false;   // only entry point for new mass

    // boundary snapshot for NEXT step (pre-rescale value + current exponent)
    S.pAr   = __shfl_up_sync(0xffffffffu, S.a[7], 1);
    S.eprev = __shfl_up_sync(0xffffffffu, S.elane, 1);
    if (lane == 0) { S.pAr = 0.f; S.eprev = S.elane; }

    if (RESC) {   // branch-free per-lane power-of-2 renormalization
        float m = fmaxf(fmaxf(fmaxf(S.a[0], S.a[1]), fmaxf(S.a[2], S.a[3])),
                        fmaxf(fmaxf(S.a[4], S.a[5]),
                              fmaxf(fmaxf(S.a[6], S.a[7]), S.a[8])));
        bool nz = m > 0.f;
        int e = nz ? (((__float_as_int(m) >> 23) & 255) - 127) : 0;
        float sc = exp2c(-e);
#pragma unroll
        for (int j = 0; j < 9; j++) S.a[j] *= sc;
        S.elane += e;
        S.empty = !nz;
    }
}

template <int SLOT>
static __device__ __forceinline__ void gather_slot(const WState& S, float (&g)[5])
{
    g[0] = lds_imm<SLOT * EMROW>(S.emu);
    g[1] = lds_imm<SLOT * EMROW>(S.coL[0]);
    g[2] = lds_imm<SLOT * EMROW>(S.coL[1]);
    g[3] = lds_imm<SLOT * EMROW>(S.coL[2]);
    g[4] = lds_imm<SLOT * EMROW>(S.coL[3]);
}
static __device__ __forceinline__ void ctc_step_rt(WState& S, int lane, unsigned off)
{
    float g[5];
    g[0] = lds_reg(S.emu + off);
    g[1] = lds_reg(S.coL[0] + off);
    g[2] = lds_reg(S.coL[1] + off);
    g[3] = lds_reg(S.coL[2] + off);
    g[4] = lds_reg(S.coL[3] + off);
    ctc_core<true>(S, lane, g);
}

// One 4-step block: gathers HOISTED to block top (all 4 slots' rows are resident
// at block entry; same-warp LSU program order makes read-before-overwrite safe).
// Steps tb..tb+3 (slots 1,2,3,0), convert Q (rows tb+4..tb+7), refill Q with
// rows tb+12..tb+15.
static __device__ __forceinline__ void block4(
    WState& S, int lane, char* emb, float4 (&Q)[4], const float* gQ, int tb)
{
    const bool ld = lane < 20;
    float G[4][5];
    gather_slot<1>(S, G[0]);
    gather_slot<2>(S, G[1]);
    gather_slot<3>(S, G[2]);
    gather_slot<0>(S, G[3]);

    ctc_core<false>(S, lane, G[0]);
    if (ld) *(float4*)(emb + 1 * EMROW) = exp4(Q[0]);
    ctc_core<true >(S, lane, G[1]);
    if (ld) *(float4*)(emb + 2 * EMROW) = exp4(Q[1]);
    ctc_core<false>(S, lane, G[2]);
    if (ld) *(float4*)(emb + 3 * EMROW) = exp4(Q[2]);
    ctc_core<true >(S, lane, G[3]);
    if (ld) {
        *(float4*)(emb + 0 * EMROW) = exp4(Q[3]);
#pragma unroll
        for (int k = 0; k < 4; k++)
            if (tb + 12 + k < TT)
                Q[k] = *(const float4*)(gQ + (size_t)k * NBC);
    }
    __syncwarp();
}

__global__ __launch_bounds__(WPB * 32)
void ctc_kernel(const float* __restrict__ lp,   // (T, N, C)
                const int*   __restrict__ tgt,  // (N, S)
                const int*   __restrict__ ilen, // (N,)
                const int*   __restrict__ tlen, // (N,)
                float*       __restrict__ out,  // (N,)
                int nb)
{
    __shared__ __align__(16) float em[WPB][4][84];  // em ring (slot = row & 3)
    __shared__ float dmp[WPB][264];                 // finalize dump (257 cells)
    __shared__ int ed[WPB][32];                     // per-lane exponents

    const int lane = threadIdx.x & 31;
    const int w    = threadIdx.x >> 5;
    const int n    = blockIdx.x * WPB + w;
    if (n >= nb) return;

    char* emb = (char*)&em[w][0][0] + lane * 16;    // this lane's convert slice
    const unsigned emu = smem_u32(&em[w][0][0]);

    const int Tn = ilen[n];
    const int tl = tlen[n];

    WState S;
    S.emu = emu;
    S.m31 = (lane == 31) ? 1.f : 0.f;
    const int* trow = tgt + (size_t)n * SS;
#pragma unroll
    for (int j = 0; j < 9; j++) S.a[j] = 0.f;
#pragma unroll
    for (int jj = 0; jj < 4; jj++) {          // label cells j = 2*jj+1, s = 8*lane+j
        int k = 4 * lane + jj;                // label index, always < 128
        int c = trow[k];
        S.coL[jj] = emu + (unsigned)c * 4;
        S.sk[jj]  = (k >= 1 && trow[k - 1] != c) ? 1.f : 0.f;
    }

    const float* glane = lp + (size_t)n * CC + lane * 4;

    // ---- prologue: LDG rows 0..8, convert rows 0..4 ----
    float4 r0 = make_float4(0.f, 0.f, 0.f, 0.f);
    float4 qa[4] = {r0, r0, r0, r0}, qb[4] = {r0, r0, r0, r0};
    if (lane < 20) {
        r0 = *(const float4*)(glane);
#pragma unroll
        for (int k = 0; k < 4; k++) qa[k] = *(const float4*)(glane + (size_t)(1 + k) * NBC);
#pragma unroll
        for (int k = 0; k < 4; k++) qb[k] = *(const float4*)(glane + (size_t)(5 + k) * NBC);
    }
    if (lane < 20) *(float4*)(emb + 0 * EMROW) = exp4(r0);      // row 0 -> slot 0
    __syncwarp();

    // alpha at t=0: lattice positions 0 (blank) and 1 (first label), lane 0
    if (lane == 0) {
        S.a[0] = lds_reg(S.emu);
        S.a[1] = lds_reg(S.coL[0]);
    }
    if (lane < 20) {                                            // rows 1..3 -> slots 1..3
        *(float4*)(emb + 1 * EMROW) = exp4(qa[0]);
        *(float4*)(emb + 2 * EMROW) = exp4(qa[1]);
        *(float4*)(emb + 3 * EMROW) = exp4(qa[2]);
    }
    __syncwarp();   // init read of slot 0 done before row-4 overwrite
    if (lane < 20) {
        *(float4*)(emb + 0 * EMROW) = exp4(qa[3]);              // row 4 -> slot 0
#pragma unroll
        for (int k = 0; k < 4; k++) qa[k] = *(const float4*)(glane + (size_t)(9 + k) * NBC);
    }
    S.elane = 0;
    S.empty = (lane != 0);
    S.pAr   = __shfl_up_sync(0xffffffffu, S.a[7], 1);
    S.eprev = __shfl_up_sync(0xffffffffu, S.elane, 1);
    if (lane == 0) { S.pAr = 0.f; S.eprev = S.elane; }
    __syncwarp();

    // ---- main loop: double 4-step blocks (qb then qa) ----
    int t = 1;
    for (; t + 7 < Tn; t += 8) {
        block4(S, lane, emb, qb, glane + (size_t)(t + 12) * NBC, t);
        block4(S, lane, emb, qa, glane + (size_t)(t + 16) * NBC, t + 4);
    }
    if (t + 3 < Tn) {
        block4(S, lane, emb, qb, glane + (size_t)(t + 12) * NBC, t);
        t += 4;
    }
    // tail: <=3 steps, em rows t..t+3 already converted by the last block
    for (; t < Tn; t++)
        ctc_step_rt(S, lane, (unsigned)((t & 3) * EMROW));

    // ---- finalize ----
    __syncwarp();
#pragma unroll
    for (int j = 0; j < 8; j++)
        dmp[w][8 * lane + j] = S.a[j];
    if (lane == 31) dmp[w][256] = S.a[8];
    ed[w][lane] = S.elane;
    __syncwarp();
    if (lane == 0) {
        int s1 = 2 * tl, s2 = s1 - 1;
        float va = dmp[w][s1]; int ea = ed[w][min(s1 >> 3, 31)];
        float vb = dmp[w][s2]; int eb = ed[w][s2 >> 3];
        int emax = max(ea, eb);
        float v = va * exp2c(ea - emax) + vb * exp2c(eb - emax);
        float loss = -((__log2f(v) + (float)emax) * 0.69314718055994530942f);
        if (!isfinite(loss) || !(loss < 1e10f)) loss = 0.f;  // zero_infinity
        out[n] = loss;
    }
}

extern "C" void kernel_launch(void* const* d_in, const int* in_sizes, int n_in,
                              void* d_out, int out_size) {
    const float* lp   = (const float*)d_in[0];
    const int*   tgt  = (const int*)d_in[1];
    const int*   ilen = (const int*)d_in[2];
    const int*   tlen = (const int*)d_in[3];
    float*       out  = (float*)d_out;
    int nb = out_size;                 // N
    int blocks = (nb + WPB - 1) / WPB; // 128
    ctc_kernel<<<blocks, WPB * 32>>>(lp, tgt, ilen, tlen, out, nb);
}